// round 1
// baseline (speedup 1.0000x reference)
#include <cuda_runtime.h>
#include <cstdint>

// Problem constants
#define Bv 32
#define Fv 256
#define Tv 2048
#define Kv 1024

#define TILE_T 64     // tokens per block
#define KC 64         // codes per smem chunk
#define WPAD 68       // padded row stride (floats) for transposed W chunk
#define NBLOCKS ((Tv / TILE_T) * Bv)   // 1024

// Scratch (no allocations allowed in kernel_launch)
__device__ float g_w2[Kv];
__device__ float g_partials[NBLOCKS];

// ---------------------------------------------------------------------------
// Kernel 1: per-code squared norms |w_k|^2 (warp per code, coalesced)
// ---------------------------------------------------------------------------
__global__ void vq_w2_kernel(const float* __restrict__ w) {
    int gtid = blockIdx.x * blockDim.x + threadIdx.x;
    int code = gtid >> 5;
    int lane = gtid & 31;
    if (code >= Kv) return;
    const float* row = w + (size_t)code * Fv;
    float s = 0.f;
    #pragma unroll
    for (int f = lane; f < Fv; f += 32) {
        float v = __ldg(row + f);
        s = fmaf(v, v, s);
    }
    #pragma unroll
    for (int o = 16; o > 0; o >>= 1) s += __shfl_down_sync(0xffffffffu, s, o);
    if (lane == 0) g_w2[code] = s;
}

// ---------------------------------------------------------------------------
// Kernel 2: fused dist + argmin + gather-write, per-block loss partial.
//
// Block: 256 threads as 16(tx: token groups) x 16(ty: code lanes).
// Each thread owns a 4-token x 4-code register tile.
// ---------------------------------------------------------------------------
extern __shared__ float smem[];

__global__ void __launch_bounds__(256, 1)
vq_main_kernel(const float* __restrict__ x,
               const float* __restrict__ w,
               float* __restrict__ out) {
    float* xs = smem;                        // [Fv][TILE_T] = 16384 floats
    float* ws = smem + Fv * TILE_T;          // [Fv][WPAD]   = 17408 floats
    int*   idx_sm  = (int*)(ws + Fv * WPAD); // [TILE_T]
    float* mind_sm = (float*)(idx_sm + TILE_T);

    const int tid = threadIdx.x;
    const int tx = tid & 15;                 // token group: tokens tx*4 .. tx*4+3
    const int ty = tid >> 4;                 // code lane:   codes  ty*4 .. ty*4+3 (within chunk)
    const int b  = blockIdx.y;
    const int t0 = blockIdx.x * TILE_T;

    // ---- load x tile [F][64], coalesced along t ----
    const float* xg = x + (size_t)b * Fv * Tv + t0;
    #pragma unroll
    for (int i = tid; i < Fv * TILE_T; i += 256) {
        int f = i >> 6, tok = i & 63;
        xs[i] = xg[(size_t)f * Tv + tok];    // xs index = f*64 + tok = i
    }

    float smin[4];
    int   sidx[4];
    #pragma unroll
    for (int j = 0; j < 4; ++j) { smin[j] = 3.4e38f; sidx[j] = 0; }

    const float4* xs4 = (const float4*)xs;

    for (int kc = 0; kc < Kv; kc += KC) {
        __syncthreads();  // protect ws from prior-iteration readers; also covers x-load on iter 0
        // ---- stage W chunk transposed: ws[f*WPAD + k] = w[kc+k][f] ----
        #pragma unroll
        for (int i = tid; i < KC * Fv; i += 256) {
            int k = i >> 8, f = i & 255;     // consecutive threads -> consecutive f (coalesced)
            ws[f * WPAD + k] = __ldg(w + (size_t)(kc + k) * Fv + f);
        }
        __syncthreads();

        float acc[4][4];
        #pragma unroll
        for (int c = 0; c < 4; ++c)
            #pragma unroll
            for (int j = 0; j < 4; ++j) acc[c][j] = 0.f;

        const float4* ws4 = (const float4*)ws;
        #pragma unroll 8
        for (int f = 0; f < Fv; ++f) {
            float4 xv = xs4[f * 16 + tx];    // 4 tokens (conflict-free, broadcast over ty)
            float4 wv = ws4[f * 17 + ty];    // 4 codes  (broadcast over tx)
            acc[0][0] = fmaf(wv.x, xv.x, acc[0][0]);
            acc[0][1] = fmaf(wv.x, xv.y, acc[0][1]);
            acc[0][2] = fmaf(wv.x, xv.z, acc[0][2]);
            acc[0][3] = fmaf(wv.x, xv.w, acc[0][3]);
            acc[1][0] = fmaf(wv.y, xv.x, acc[1][0]);
            acc[1][1] = fmaf(wv.y, xv.y, acc[1][1]);
            acc[1][2] = fmaf(wv.y, xv.z, acc[1][2]);
            acc[1][3] = fmaf(wv.y, xv.w, acc[1][3]);
            acc[2][0] = fmaf(wv.z, xv.x, acc[2][0]);
            acc[2][1] = fmaf(wv.z, xv.y, acc[2][1]);
            acc[2][2] = fmaf(wv.z, xv.z, acc[2][2]);
            acc[2][3] = fmaf(wv.z, xv.w, acc[2][3]);
            acc[3][0] = fmaf(wv.w, xv.x, acc[3][0]);
            acc[3][1] = fmaf(wv.w, xv.y, acc[3][1]);
            acc[3][2] = fmaf(wv.w, xv.z, acc[3][2]);
            acc[3][3] = fmaf(wv.w, xv.w, acc[3][3]);
        }

        // ---- score = |w_k|^2 - 2*x.w_k ; track min/argmin (ascending k within thread) ----
        #pragma unroll
        for (int c = 0; c < 4; ++c) {
            int k = kc + ty * 4 + c;
            float w2 = __ldg(&g_w2[k]);
            #pragma unroll
            for (int j = 0; j < 4; ++j) {
                float s = fmaf(-2.f, acc[c][j], w2);
                if (s < smin[j]) { smin[j] = s; sidx[j] = k; }
            }
        }
    }
    __syncthreads();

    // ---- cross-thread (ty) reduction; tie -> lower index (matches jnp.argmin) ----
    float* red_s = ws;                       // [16][64], reuses ws region
    int*   red_i = (int*)(ws + 16 * 64);
    #pragma unroll
    for (int j = 0; j < 4; ++j) {
        red_s[ty * 64 + tx * 4 + j] = smin[j];
        red_i[ty * 64 + tx * 4 + j] = sidx[j];
    }
    __syncthreads();

    if (tid < TILE_T) {
        int tok = tid;
        float bs = red_s[tok];
        int   bi = red_i[tok];
        #pragma unroll
        for (int u = 1; u < 16; ++u) {
            float s  = red_s[u * 64 + tok];
            int   i2 = red_i[u * 64 + tok];
            if (s < bs || (s == bs && i2 < bi)) { bs = s; bi = i2; }
        }
        // |x|^2 for the loss value
        float x2 = 0.f;
        #pragma unroll 8
        for (int f = 0; f < Fv; ++f) { float v = xs[f * 64 + tok]; x2 = fmaf(v, v, x2); }
        idx_sm[tok]  = bi;
        mind_sm[tok] = (x2 + bs) * (1.0f / (float)Fv);
    }
    __syncthreads();

    if (tid == 0) {
        float s = 0.f;
        #pragma unroll
        for (int tok = 0; tok < TILE_T; ++tok) s += mind_sm[tok];
        g_partials[blockIdx.y * gridDim.x + blockIdx.x] = s;
    }

    // ---- epilogue: out[b][f][t0+tok] = w[idx[tok]][f], write-coalesced ----
    {
        int tok = tid & 63;
        int fg  = tid >> 6;                  // 0..3, each covers 64 features
        int myidx = idx_sm[tok];
        const float* wr = w + (size_t)myidx * Fv + fg * 64;
        float* og = out + (size_t)b * Fv * Tv + (size_t)(fg * 64) * Tv + t0 + tok;
        #pragma unroll 4
        for (int i = 0; i < 64; ++i) {
            og[(size_t)i * Tv] = __ldg(wr + i);
        }
    }
}

// ---------------------------------------------------------------------------
// Kernel 3: deterministic loss reduction (both losses are numerically equal)
// ---------------------------------------------------------------------------
__global__ void vq_loss_kernel(float* __restrict__ out, int out_size) {
    __shared__ float sh[256];
    float s = 0.f;
    for (int i = threadIdx.x; i < NBLOCKS; i += 256) s += g_partials[i];
    sh[threadIdx.x] = s;
    __syncthreads();
    #pragma unroll
    for (int o = 128; o > 0; o >>= 1) {
        if (threadIdx.x < o) sh[threadIdx.x] += sh[threadIdx.x + o];
        __syncthreads();
    }
    if (threadIdx.x == 0) {
        float mean = sh[0] / (float)(Bv * Tv);
        const long long N = (long long)Bv * Fv * Tv;
        if (out_size > N)     out[N]     = mean;  // loss_commit
        if (out_size > N + 1) out[N + 1] = mean;  // loss_codebook (identical value)
    }
}

// ---------------------------------------------------------------------------
extern "C" void kernel_launch(void* const* d_in, const int* in_sizes, int n_in,
                              void* d_out, int out_size) {
    const float* x = (const float*)d_in[0];         // [B, F, T]
    const float* w = (const float*)d_in[1];         // [K, F]
    float* out = (float*)d_out;

    const int smem_bytes = (Fv * TILE_T + Fv * WPAD) * 4 + TILE_T * 4 + TILE_T * 4;
    cudaFuncSetAttribute(vq_main_kernel,
                         cudaFuncAttributeMaxDynamicSharedMemorySize, smem_bytes);

    // |w_k|^2 precompute: 1024 codes * 32 lanes = 32768 threads
    vq_w2_kernel<<<32, 1024>>>(w);

    dim3 grid(Tv / TILE_T, Bv);                     // (32, 32) = 1024 blocks
    vq_main_kernel<<<grid, 256, smem_bytes>>>(x, w, out);

    vq_loss_kernel<<<1, 256>>>(out, out_size);
}

// round 4
// speedup vs baseline: 1.9874x; 1.9874x over previous
#include <cuda_runtime.h>
#include <cuda_fp16.h>
#include <cstdint>

#define Bv 32
#define Fv 256
#define Tv 2048
#define Kv 1024
#define MTOT (Bv * Tv)   // 65536

// ---------------- device scratch (no allocs allowed) ----------------
__device__ __half g_xh[(size_t)MTOT * Fv];
__device__ __half g_xl[(size_t)MTOT * Fv];
__device__ __half g_wh[Kv * Fv];
__device__ float  g_w2[Kv];
__device__ float  g_x2[MTOT];
__device__ float  g_xh2[MTOT];
__device__ float  g_xl2[MTOT];
__device__ float  g_mind[MTOT];
__device__ int    g_idx[MTOT];
__device__ int    g_list[MTOT];
__device__ int    g_n1;
__device__ unsigned g_w2max, g_wl2max;

// ---------------- helpers ----------------
__device__ __forceinline__ uint32_t s2u(const void* p) {
    return (uint32_t)__cvta_generic_to_shared(p);
}
__device__ __forceinline__ void cp16(uint32_t dst, const void* src) {
    asm volatile("cp.async.cg.shared.global [%0], [%1], 16;\n" :: "r"(dst), "l"(src) : "memory");
}
__device__ __forceinline__ void cp_commit() {
    asm volatile("cp.async.commit_group;\n" ::: "memory");
}
template <int N> __device__ __forceinline__ void cp_wait() {
    asm volatile("cp.async.wait_group %0;\n" :: "n"(N) : "memory");
}
__device__ __forceinline__ void ldsm4(uint32_t* r, uint32_t a) {
    asm volatile("ldmatrix.sync.aligned.m8n8.x4.shared.b16 {%0,%1,%2,%3}, [%4];\n"
                 : "=r"(r[0]), "=r"(r[1]), "=r"(r[2]), "=r"(r[3]) : "r"(a));
}
__device__ __forceinline__ void mma16816(float* c, const uint32_t* a, uint32_t b0, uint32_t b1) {
    asm volatile("mma.sync.aligned.m16n8k16.row.col.f32.f16.f16.f32 "
                 "{%0,%1,%2,%3}, {%4,%5,%6,%7}, {%8,%9}, {%0,%1,%2,%3};\n"
                 : "+f"(c[0]), "+f"(c[1]), "+f"(c[2]), "+f"(c[3])
                 : "r"(a[0]), "r"(a[1]), "r"(a[2]), "r"(a[3]), "r"(b0), "r"(b1));
}
// SMEM rows of 256 fp16 (512B), 16B chunks XOR-swizzled
__device__ __forceinline__ uint32_t swoff(int r, int ch) {
    return (uint32_t)r * 512u + (uint32_t)((ch ^ (r & 7)) << 4);
}
__device__ __forceinline__ void mergePair(float& m1, int& i1, float& m2,
                                          float om1, int oi1, float om2) {
    if (om1 < m1 || (om1 == m1 && oi1 < i1)) {
        m2 = fminf(m1, fminf(m2, om2)); m1 = om1; i1 = oi1;
    } else {
        m2 = fminf(om1, fminf(m2, om2));
    }
}

// ---------------- zero counters (every replay) ----------------
__global__ void zero_init() { g_n1 = 0; g_w2max = 0u; g_wl2max = 0u; }

// ---------------- W prep: wh fp16, |w|^2, maxima ----------------
__global__ void __launch_bounds__(256) w_prep(const float* __restrict__ w) {
    __shared__ float s2[256], sl[256];
    int c = blockIdx.x, f = threadIdx.x;
    float v = w[(size_t)c * Fv + f];
    __half hi = __float2half_rn(v);
    g_wh[c * Fv + f] = hi;
    float le = v - __half2float(hi);
    s2[f] = v * v;
    sl[f] = le * le;
    __syncthreads();
    #pragma unroll
    for (int o = 128; o > 0; o >>= 1) {
        if (f < o) { s2[f] += s2[f + o]; sl[f] += sl[f + o]; }
        __syncthreads();
    }
    if (f == 0) {
        g_w2[c] = s2[0];
        atomicMax(&g_w2max, __float_as_uint(s2[0]));
        atomicMax(&g_wl2max, __float_as_uint(sl[0]));
    }
}

// ---------------- X prep: transpose + hi/lo fp16 + norms ----------------
__global__ void __launch_bounds__(256) x_prep(const float* __restrict__ x) {
    extern __shared__ float xs[];                  // [256][65]
    int bb = blockIdx.x >> 5, t0 = (blockIdx.x & 31) * 64;
    const float* xg = x + (size_t)bb * Fv * Tv + t0;
    int tid = threadIdx.x;
    for (int i = tid; i < Fv * 64; i += 256) {
        int f = i >> 6, tt = i & 63;
        xs[f * 65 + tt] = xg[(size_t)f * Tv + tt];
    }
    __syncthreads();
    size_t g0 = (size_t)bb * Tv + t0;
    for (int i = tid; i < 64 * Fv; i += 256) {
        int tok = i >> 8, f = i & 255;
        float v = xs[f * 65 + tok];
        __half hi = __float2half_rn(v);
        size_t gi = (g0 + tok) * Fv + f;
        g_xh[gi] = hi;
        g_xl[gi] = __float2half_rn(v - __half2float(hi));
    }
    int wrp = tid >> 5, l = tid & 31;
    #pragma unroll
    for (int it = 0; it < 8; it++) {
        int tok = it * 8 + wrp;
        float s = 0.f, sh = 0.f, slo = 0.f;
        #pragma unroll 8
        for (int f = l; f < Fv; f += 32) {
            float v = xs[f * 65 + tok];
            float vh = __half2float(__float2half_rn(v));
            float vl = __half2float(__float2half_rn(v - vh));
            s = fmaf(v, v, s); sh = fmaf(vh, vh, sh); slo = fmaf(vl, vl, slo);
        }
        #pragma unroll
        for (int o = 16; o > 0; o >>= 1) {
            s   += __shfl_down_sync(0xffffffffu, s, o);
            sh  += __shfl_down_sync(0xffffffffu, sh, o);
            slo += __shfl_down_sync(0xffffffffu, slo, o);
        }
        if (l == 0) { g_x2[g0 + tok] = s; g_xh2[g0 + tok] = sh; g_xl2[g0 + tok] = slo; }
    }
}

// ---------------- Stage A: hi-only HMMA GEMM + min1/min2 + flag ----------------
#define SA_A   0          // 64 KB: 128 token rows
#define SA_B   65536      // 2 x 32 KB: 64-code chunks
#define SA_W2  131072     // 4 KB
#define SA_RED 135168     // 2x128 x (f,i,f) = 3 KB
#define SA_TOTAL 138240

__global__ void __launch_bounds__(256, 1) vq_hmma() {
    extern __shared__ char sm[];
    const uint32_t sb = s2u(sm);
    const int tid = threadIdx.x, lane = tid & 31, wid = tid >> 5;
    const int wm = wid & 3, wn = wid >> 2;
    const int m0 = blockIdx.x * 128;

    #pragma unroll
    for (int p = 0; p < 16; p++) {                 // A: xh 128x256
        int i = p * 256 + tid, r = i >> 5, ch = i & 31;
        cp16(sb + SA_A + swoff(r, ch), g_xh + (size_t)(m0 + r) * Fv + ch * 8);
    }
    #pragma unroll
    for (int p = 0; p < 8; p++) {                  // B chunk0 -> buf0
        int i = p * 256 + tid, r = i >> 5, ch = i & 31;
        cp16(sb + SA_B + swoff(r, ch), g_wh + (size_t)r * Fv + ch * 8);
    }
    cp_commit();

    float* w2s = (float*)(sm + SA_W2);
    for (int i = tid; i < Kv; i += 256) w2s[i] = g_w2[i];

    float mn1[4], mn2[4]; int mi1[4];
    #pragma unroll
    for (int r = 0; r < 4; r++) { mn1[r] = 3.4e38f; mn2[r] = 3.4e38f; mi1[r] = 0; }

    const uint32_t arow = sb + SA_A + (uint32_t)(wm * 32 + (lane & 15)) * 512;
    const uint32_t browoff = (uint32_t)(wn * 32 + (lane & 15)) * 512;
    const int xr = lane & 7, hsel = lane >> 4;

    for (int c = 0; c < 16; c++) {
        __syncthreads();
        if (c + 1 < 16) {
            int buf = (c + 1) & 1;
            const __half* src = g_wh + (size_t)(c + 1) * 64 * Fv;
            #pragma unroll
            for (int p = 0; p < 8; p++) {
                int i = p * 256 + tid, r = i >> 5, ch = i & 31;
                cp16(sb + SA_B + buf * 32768 + swoff(r, ch), src + (size_t)r * Fv + ch * 8);
            }
            cp_commit();
            cp_wait<1>();
        } else cp_wait<0>();
        __syncthreads();

        const uint32_t bbase = sb + SA_B + (c & 1) * 32768 + browoff;
        float acc[2][4][4];
        #pragma unroll
        for (int a = 0; a < 2; a++)
            #pragma unroll
            for (int b = 0; b < 4; b++)
                #pragma unroll
                for (int j = 0; j < 4; j++) acc[a][b][j] = 0.f;

        #pragma unroll 4
        for (int ks = 0; ks < 16; ks++) {
            uint32_t sw = (uint32_t)(((2 * ks + hsel) ^ xr) << 4);
            uint32_t a0[4], a1[4], b0[4], b1[4];
            ldsm4(a0, arow + sw);
            ldsm4(a1, arow + 16 * 512 + sw);
            ldsm4(b0, bbase + sw);
            ldsm4(b1, bbase + 16 * 512 + sw);
            mma16816(acc[0][0], a0, b0[0], b0[2]);
            mma16816(acc[0][1], a0, b0[1], b0[3]);
            mma16816(acc[0][2], a0, b1[0], b1[2]);
            mma16816(acc[0][3], a0, b1[1], b1[3]);
            mma16816(acc[1][0], a1, b0[0], b0[2]);
            mma16816(acc[1][1], a1, b0[1], b0[3]);
            mma16816(acc[1][2], a1, b1[0], b1[2]);
            mma16816(acc[1][3], a1, b1[1], b1[3]);
        }
        int kb = c * 64 + wn * 32 + 2 * (lane & 3);
        #pragma unroll
        for (int mt = 0; mt < 2; mt++)
            #pragma unroll
            for (int nt = 0; nt < 4; nt++) {
                int kk = kb + nt * 8;
                #pragma unroll
                for (int j = 0; j < 4; j++) {
                    float sv = fmaf(-2.f, acc[mt][nt][j], w2s[kk + (j & 1)]);
                    int r = mt * 2 + (j >> 1);
                    if (sv < mn1[r]) { mn2[r] = mn1[r]; mn1[r] = sv; mi1[r] = kk + (j & 1); }
                    else if (sv < mn2[r]) mn2[r] = sv;
                }
            }
    }

    #pragma unroll
    for (int r = 0; r < 4; r++)
        #pragma unroll
        for (int d = 1; d <= 2; d <<= 1) {
            float om1 = __shfl_xor_sync(0xffffffffu, mn1[r], d);
            int   oi1 = __shfl_xor_sync(0xffffffffu, mi1[r], d);
            float om2 = __shfl_xor_sync(0xffffffffu, mn2[r], d);
            mergePair(mn1[r], mi1[r], mn2[r], om1, oi1, om2);
        }
    float* r1s = (float*)(sm + SA_RED);
    int*   ris = (int*)(sm + SA_RED + 1024);
    float* r2s = (float*)(sm + SA_RED + 2048);
    __syncthreads();
    if ((lane & 3) == 0) {
        #pragma unroll
        for (int r = 0; r < 4; r++) {
            int row = wm * 32 + (r >> 1) * 16 + (r & 1) * 8 + (lane >> 2);
            r1s[wn * 128 + row] = mn1[r]; ris[wn * 128 + row] = mi1[r]; r2s[wn * 128 + row] = mn2[r];
        }
    }
    __syncthreads();
    if (tid < 128) {
        float m1 = r1s[tid], m2 = r2s[tid]; int i1 = ris[tid];
        mergePair(m1, i1, m2, r1s[128 + tid], ris[128 + tid], r2s[128 + tid]);
        int tok = m0 + tid;
        g_idx[tok]  = i1;
        g_mind[tok] = (g_x2[tok] + m1) * (1.0f / (float)Fv);
        float WL = sqrtf(__uint_as_float(g_wl2max)), WM = sqrtf(__uint_as_float(g_w2max));
        float bnd = 2.002f * (sqrtf(g_xh2[tok]) * WL + sqrtf(g_xl2[tok]) * WM) + 0.05f;
        if (m2 - m1 <= bnd) g_list[atomicAdd(&g_n1, 1)] = tok;
    }
}

// ---------------- Stage B: exact fp32 re-scan of flagged tokens ----------------
#define FIX_SMEM (8 * 256 * 4 + 64 * 257 * 4 + 8 * 64 * 8)
__global__ void __launch_bounds__(256, 1) vq_fix(const float* __restrict__ w,
                                                 const float* __restrict__ x) {
    extern __shared__ float fsm[];
    float* xs = fsm;                               // [8][256]
    float* ws = fsm + 2048;                        // [64][257]
    float* reds = fsm + 2048 + 64 * 257;           // [8][64]
    int*   redi = (int*)(reds + 512);
    __shared__ int tk[8];
    const int tid = threadIdx.x;
    const int n1 = g_n1;
    const int cl = tid & 63, tg = tid >> 6;

    for (int g = blockIdx.x * 8; g < n1; g += gridDim.x * 8) {
        int nt = min(8, n1 - g);
        __syncthreads();
        if (tid < 8) tk[tid] = g_list[(g + tid < n1) ? (g + tid) : g];
        __syncthreads();
        for (int i = tid; i < nt * 256; i += 256) {
            int tl = i >> 8, f = i & 255;
            int tok = tk[tl];
            xs[tl * 256 + f] = x[((size_t)(tok >> 11) * Fv + f) * Tv + (tok & 2047)];
        }
        float bs0 = 3.4e38f, bs1 = 3.4e38f; int bi0 = 0, bi1 = 0;
        for (int ch = 0; ch < 16; ch++) {
            __syncthreads();
            for (int i = tid; i < 64 * 256; i += 256) {
                int r = i >> 8, f = i & 255;
                ws[r * 257 + f] = w[(size_t)(ch * 64 + r) * Fv + f];
            }
            __syncthreads();
            int k = ch * 64 + cl;
            float w2v = __ldg(&g_w2[k]);
            float d0 = 0.f, d1 = 0.f;
            const float* wr = ws + cl * 257;
            const float* x0 = xs + (tg * 2) * 256;
            const float* x1 = x0 + 256;
            #pragma unroll 8
            for (int f = 0; f < 256; f++) {
                float wv = wr[f];
                d0 = fmaf(wv, x0[f], d0);
                d1 = fmaf(wv, x1[f], d1);
            }
            float s0 = fmaf(-2.f, d0, w2v), s1 = fmaf(-2.f, d1, w2v);
            if (s0 < bs0) { bs0 = s0; bi0 = k; }
            if (s1 < bs1) { bs1 = s1; bi1 = k; }
        }
        __syncthreads();
        reds[(tg * 2) * 64 + cl] = bs0;     redi[(tg * 2) * 64 + cl] = bi0;
        reds[(tg * 2 + 1) * 64 + cl] = bs1; redi[(tg * 2 + 1) * 64 + cl] = bi1;
        __syncthreads();
        if (tid < nt) {
            float bs = reds[tid * 64]; int bi = redi[tid * 64];
            #pragma unroll 8
            for (int u = 1; u < 64; u++) {
                float s = reds[tid * 64 + u]; int ii = redi[tid * 64 + u];
                if (s < bs || (s == bs && ii < bi)) { bs = s; bi = ii; }
            }
            int tok = tk[tid];
            g_idx[tok]  = bi;
            g_mind[tok] = (g_x2[tok] + bs) * (1.0f / (float)Fv);
        }
    }
}

// ---------------- gather: out[b][f][t] = w[idx][f] (exact fp32) ----------------
__global__ void __launch_bounds__(256) vq_gather(const float* __restrict__ w,
                                                 float* __restrict__ out) {
    int m0 = blockIdx.x * 128;
    int tok = threadIdx.x & 127, fg = threadIdx.x >> 7;
    int k = g_idx[m0 + tok];
    int bb = m0 >> 11, t = (m0 & 2047) + tok;
    const float* wr = w + (size_t)k * Fv + fg * 128;
    float* og = out + (size_t)bb * Fv * Tv + (size_t)(fg * 128) * Tv + t;
    #pragma unroll 4
    for (int i = 0; i < 128; i++) og[(size_t)i * Tv] = __ldg(wr + i);
}

// ---------------- loss (deterministic fixed-order reduction) ----------------
__global__ void __launch_bounds__(256) vq_loss(float* __restrict__ out, int out_size) {
    __shared__ float sh[256];
    float s = 0.f;
    for (int i = threadIdx.x; i < MTOT; i += 256) s += g_mind[i];
    sh[threadIdx.x] = s;
    __syncthreads();
    #pragma unroll
    for (int o = 128; o > 0; o >>= 1) {
        if (threadIdx.x < o) sh[threadIdx.x] += sh[threadIdx.x + o];
        __syncthreads();
    }
    if (threadIdx.x == 0) {
        float mean = sh[0] / (float)MTOT;
        const long long N = (long long)Bv * Fv * Tv;
        if (out_size > N)     out[N]     = mean;
        if (out_size > N + 1) out[N + 1] = mean;
    }
}

// ---------------------------------------------------------------------------
extern "C" void kernel_launch(void* const* d_in, const int* in_sizes, int n_in,
                              void* d_out, int out_size) {
    const float* x = (const float*)d_in[0];
    const float* w = (const float*)d_in[1];
    float* out = (float*)d_out;

    cudaFuncSetAttribute(x_prep, cudaFuncAttributeMaxDynamicSharedMemorySize, 256 * 65 * 4);
    cudaFuncSetAttribute(vq_hmma, cudaFuncAttributeMaxDynamicSharedMemorySize, SA_TOTAL);
    cudaFuncSetAttribute(vq_fix, cudaFuncAttributeMaxDynamicSharedMemorySize, FIX_SMEM);

    zero_init<<<1, 1>>>();
    w_prep<<<Kv, 256>>>(w);
    x_prep<<<MTOT / 64, 256, 256 * 65 * 4>>>(x);
    vq_hmma<<<MTOT / 128, 256, SA_TOTAL>>>();
    vq_fix<<<256, 256, FIX_SMEM>>>(w, x);
    vq_gather<<<MTOT / 128, 256>>>(w, out);
    vq_loss<<<1, 256>>>(out, out_size);
}

// round 5
// speedup vs baseline: 2.6785x; 1.3477x over previous
#include <cuda_runtime.h>
#include <cuda_fp16.h>
#include <cstdint>

#define Bv 32
#define Fv 256
#define Tv 2048
#define Kv 1024
#define MTOT (Bv * Tv)   // 65536

// ---------------- device scratch (no allocs allowed) ----------------
__device__ __half g_xh[(size_t)MTOT * Fv];    // 32 MB fp16 hi(x), [token][f]
__device__ float  g_xT[(size_t)MTOT * Fv];    // 64 MB fp32 x, [token][f]
__device__ __half g_wh[Kv * Fv];
__device__ float  g_w2[Kv];
__device__ float  g_x2[MTOT];
__device__ float  g_xh2[MTOT];
__device__ float  g_xl2[MTOT];
__device__ float  g_mind[MTOT];
__device__ int    g_idx[MTOT];
__device__ int    g_list[MTOT];
__device__ int    g_n1;
__device__ unsigned g_w2max, g_wl2max;
__device__ float  g_fs[2048][16][32];
__device__ int    g_fi[2048][16][32];
__device__ float  g_lpart[64];

// ---------------- helpers ----------------
__device__ __forceinline__ uint32_t s2u(const void* p) {
    return (uint32_t)__cvta_generic_to_shared(p);
}
__device__ __forceinline__ void cp16(uint32_t dst, const void* src) {
    asm volatile("cp.async.cg.shared.global [%0], [%1], 16;\n" :: "r"(dst), "l"(src) : "memory");
}
__device__ __forceinline__ void cp_commit() {
    asm volatile("cp.async.commit_group;\n" ::: "memory");
}
template <int N> __device__ __forceinline__ void cp_wait() {
    asm volatile("cp.async.wait_group %0;\n" :: "n"(N) : "memory");
}
__device__ __forceinline__ void ldsm4(uint32_t* r, uint32_t a) {
    asm volatile("ldmatrix.sync.aligned.m8n8.x4.shared.b16 {%0,%1,%2,%3}, [%4];\n"
                 : "=r"(r[0]), "=r"(r[1]), "=r"(r[2]), "=r"(r[3]) : "r"(a));
}
__device__ __forceinline__ void mma16816(float* c, const uint32_t* a, uint32_t b0, uint32_t b1) {
    asm volatile("mma.sync.aligned.m16n8k16.row.col.f32.f16.f16.f32 "
                 "{%0,%1,%2,%3}, {%4,%5,%6,%7}, {%8,%9}, {%0,%1,%2,%3};\n"
                 : "+f"(c[0]), "+f"(c[1]), "+f"(c[2]), "+f"(c[3])
                 : "r"(a[0]), "r"(a[1]), "r"(a[2]), "r"(a[3]), "r"(b0), "r"(b1));
}
__device__ __forceinline__ uint32_t swoff(int r, int ch) {
    return (uint32_t)r * 512u + (uint32_t)((ch ^ (r & 7)) << 4);
}
__device__ __forceinline__ void mergePair(float& m1, int& i1, float& m2,
                                          float om1, int oi1, float om2) {
    if (om1 < m1 || (om1 == m1 && oi1 < i1)) {
        m2 = fminf(m1, fminf(m2, om2)); m1 = om1; i1 = oi1;
    } else {
        m2 = fminf(om1, fminf(m2, om2));
    }
}

// ---------------- zero counters (every replay) ----------------
__global__ void zero_init() { g_n1 = 0; g_w2max = 0u; g_wl2max = 0u; }

// ---------------- W prep ----------------
__global__ void __launch_bounds__(256) w_prep(const float* __restrict__ w) {
    __shared__ float s2[256], sl[256];
    int c = blockIdx.x, f = threadIdx.x;
    float v = w[(size_t)c * Fv + f];
    __half hi = __float2half_rn(v);
    g_wh[c * Fv + f] = hi;
    float le = v - __half2float(hi);
    s2[f] = v * v;
    sl[f] = le * le;
    __syncthreads();
    #pragma unroll
    for (int o = 128; o > 0; o >>= 1) {
        if (f < o) { s2[f] += s2[f + o]; sl[f] += sl[f + o]; }
        __syncthreads();
    }
    if (f == 0) {
        g_w2[c] = s2[0];
        atomicMax(&g_w2max, __float_as_uint(s2[0]));
        atomicMax(&g_wl2max, __float_as_uint(sl[0]));
    }
}

// ---------------- X prep: transpose + xh fp16 + xT fp32 + norms ----------------
__global__ void __launch_bounds__(256) x_prep(const float* __restrict__ x) {
    extern __shared__ float xs[];                  // [256][65]
    int bb = blockIdx.x >> 5, t0 = (blockIdx.x & 31) * 64;
    const float* xg = x + (size_t)bb * Fv * Tv + t0;
    int tid = threadIdx.x;
    for (int i = tid; i < Fv * 64; i += 256) {
        int f = i >> 6, tt = i & 63;
        xs[f * 65 + tt] = xg[(size_t)f * Tv + tt];
    }
    __syncthreads();
    size_t g0 = (size_t)bb * Tv + t0;
    for (int i = tid; i < 64 * Fv; i += 256) {
        int tok = i >> 8, f = i & 255;
        float v = xs[f * 65 + tok];
        size_t gi = (g0 + tok) * Fv + f;
        g_xh[gi] = __float2half_rn(v);
        g_xT[gi] = v;
    }
    int wrp = tid >> 5, l = tid & 31;
    #pragma unroll
    for (int it = 0; it < 8; it++) {
        int tok = it * 8 + wrp;
        float s = 0.f, sh = 0.f, slo = 0.f;
        #pragma unroll 8
        for (int f = l; f < Fv; f += 32) {
            float v = xs[f * 65 + tok];
            float vh = __half2float(__float2half_rn(v));
            float vl = __half2float(__float2half_rn(v - vh));
            s = fmaf(v, v, s); sh = fmaf(vh, vh, sh); slo = fmaf(vl, vl, slo);
        }
        #pragma unroll
        for (int o = 16; o > 0; o >>= 1) {
            s   += __shfl_down_sync(0xffffffffu, s, o);
            sh  += __shfl_down_sync(0xffffffffu, sh, o);
            slo += __shfl_down_sync(0xffffffffu, slo, o);
        }
        if (l == 0) { g_x2[g0 + tok] = s; g_xh2[g0 + tok] = sh; g_xl2[g0 + tok] = slo; }
    }
}

// ---------------- Stage A: hi-only HMMA GEMM, M=128 x N=128 tiles ----------------
#define SA_A    0          // 64 KB
#define SA_B    65536      // 2 x 64 KB (128-code chunks)
#define SA_W2   196608     // 4 KB
#define SA_RED  200704     // 4 groups x 128 x 12B = 6 KB
#define SA_TOTAL 206848

__global__ void __launch_bounds__(512, 1) vq_hmma() {
    extern __shared__ char sm[];
    const uint32_t sb = s2u(sm);
    const int tid = threadIdx.x, lane = tid & 31, wid = tid >> 5;
    const int wm = wid & 3, wn = wid >> 2;         // 4 x 4 warp grid
    const int m0 = blockIdx.x * 128;

    #pragma unroll
    for (int p = 0; p < 8; p++) {                  // A: xh 128x256
        int i = p * 512 + tid, r = i >> 5, ch = i & 31;
        cp16(sb + SA_A + swoff(r, ch), g_xh + (size_t)(m0 + r) * Fv + ch * 8);
    }
    #pragma unroll
    for (int p = 0; p < 8; p++) {                  // B chunk0 (128 codes)
        int i = p * 512 + tid, r = i >> 5, ch = i & 31;
        cp16(sb + SA_B + swoff(r, ch), g_wh + (size_t)r * Fv + ch * 8);
    }
    cp_commit();

    float* w2s = (float*)(sm + SA_W2);
    for (int i = tid; i < Kv; i += 512) w2s[i] = g_w2[i];

    float mn1[4], mn2[4]; int mi1[4];
    #pragma unroll
    for (int r = 0; r < 4; r++) { mn1[r] = 3.4e38f; mn2[r] = 3.4e38f; mi1[r] = 0; }

    const uint32_t arow = sb + SA_A + (uint32_t)(wm * 32 + (lane & 15)) * 512;
    const uint32_t browoff = (uint32_t)(wn * 32 + (lane & 15)) * 512;
    const int xr = lane & 7, hsel = lane >> 4;

    for (int c = 0; c < 8; c++) {
        __syncthreads();
        if (c + 1 < 8) {
            int buf = (c + 1) & 1;
            const __half* src = g_wh + (size_t)(c + 1) * 128 * Fv;
            #pragma unroll
            for (int p = 0; p < 8; p++) {
                int i = p * 512 + tid, r = i >> 5, ch = i & 31;
                cp16(sb + SA_B + buf * 65536 + swoff(r, ch), src + (size_t)r * Fv + ch * 8);
            }
            cp_commit();
            cp_wait<1>();
        } else cp_wait<0>();
        __syncthreads();

        const uint32_t bbase = sb + SA_B + (c & 1) * 65536 + browoff;
        float acc[2][4][4];
        #pragma unroll
        for (int a = 0; a < 2; a++)
            #pragma unroll
            for (int b = 0; b < 4; b++)
                #pragma unroll
                for (int j = 0; j < 4; j++) acc[a][b][j] = 0.f;

        #pragma unroll 4
        for (int ks = 0; ks < 16; ks++) {
            uint32_t sw = (uint32_t)(((2 * ks + hsel) ^ xr) << 4);
            uint32_t a0[4], a1[4], b0[4], b1[4];
            ldsm4(a0, arow + sw);
            ldsm4(a1, arow + 16 * 512 + sw);
            ldsm4(b0, bbase + sw);
            ldsm4(b1, bbase + 16 * 512 + sw);
            mma16816(acc[0][0], a0, b0[0], b0[2]);
            mma16816(acc[0][1], a0, b0[1], b0[3]);
            mma16816(acc[0][2], a0, b1[0], b1[2]);
            mma16816(acc[0][3], a0, b1[1], b1[3]);
            mma16816(acc[1][0], a1, b0[0], b0[2]);
            mma16816(acc[1][1], a1, b0[1], b0[3]);
            mma16816(acc[1][2], a1, b1[0], b1[2]);
            mma16816(acc[1][3], a1, b1[1], b1[3]);
        }
        int kb = c * 128 + wn * 32 + 2 * (lane & 3);
        #pragma unroll
        for (int mt = 0; mt < 2; mt++)
            #pragma unroll
            for (int nt = 0; nt < 4; nt++) {
                int kk = kb + nt * 8;
                #pragma unroll
                for (int j = 0; j < 4; j++) {
                    float sv = fmaf(-2.f, acc[mt][nt][j], w2s[kk + (j & 1)]);
                    int r = mt * 2 + (j >> 1);
                    if (sv < mn1[r]) { mn2[r] = mn1[r]; mn1[r] = sv; mi1[r] = kk + (j & 1); }
                    else if (sv < mn2[r]) mn2[r] = sv;
                }
            }
    }

    #pragma unroll
    for (int r = 0; r < 4; r++)
        #pragma unroll
        for (int d = 1; d <= 2; d <<= 1) {
            float om1 = __shfl_xor_sync(0xffffffffu, mn1[r], d);
            int   oi1 = __shfl_xor_sync(0xffffffffu, mi1[r], d);
            float om2 = __shfl_xor_sync(0xffffffffu, mn2[r], d);
            mergePair(mn1[r], mi1[r], mn2[r], om1, oi1, om2);
        }
    float* r1s = (float*)(sm + SA_RED);
    int*   ris = (int*)(sm + SA_RED + 2048);
    float* r2s = (float*)(sm + SA_RED + 4096);
    __syncthreads();
    if ((lane & 3) == 0) {
        #pragma unroll
        for (int r = 0; r < 4; r++) {
            int row = wm * 32 + (r >> 1) * 16 + (r & 1) * 8 + (lane >> 2);
            r1s[wn * 128 + row] = mn1[r]; ris[wn * 128 + row] = mi1[r]; r2s[wn * 128 + row] = mn2[r];
        }
    }
    __syncthreads();
    if (tid < 128) {
        float m1 = r1s[tid], m2 = r2s[tid]; int i1 = ris[tid];
        #pragma unroll
        for (int u = 1; u < 4; u++)
            mergePair(m1, i1, m2, r1s[u * 128 + tid], ris[u * 128 + tid], r2s[u * 128 + tid]);
        int tok = m0 + tid;
        g_idx[tok]  = i1;
        g_mind[tok] = (g_x2[tok] + m1) * (1.0f / (float)Fv);
        float WL = sqrtf(__uint_as_float(g_wl2max)), WM = sqrtf(__uint_as_float(g_w2max));
        float bnd = 2.002f * (sqrtf(g_xh2[tok]) * WL + sqrtf(g_xl2[tok]) * WM) + 0.05f;
        if (m2 - m1 <= bnd) g_list[atomicAdd(&g_n1, 1)] = tok;
    }
}

// ---------------- Stage B: exact fp32 re-scan, 2D grid (chunk x group) ----------------
__global__ void __launch_bounds__(256, 2) vq_fix2(const float* __restrict__ w) {
    __shared__ float xs[32 * 256];
    __shared__ float ws[64 * 257];
    __shared__ int tk[32];
    const int tid = threadIdx.x, ch = blockIdx.x;
    const int n1 = g_n1;
    const int cl = tid & 31, tg = tid >> 5;

    for (int grp = blockIdx.y; grp * 32 < n1; grp += gridDim.y) {
        __syncthreads();
        if (tid < 32) {
            int p = grp * 32 + tid;
            tk[tid] = g_list[p < n1 ? p : (n1 - 1)];
        }
        __syncthreads();
        #pragma unroll 8
        for (int p = 0; p < 32; p++) {
            int i = p * 256 + tid;
            int tl = i >> 8, f = i & 255;
            xs[i] = g_xT[(size_t)tk[tl] * Fv + f];
        }
        #pragma unroll 8
        for (int p = 0; p < 64; p++) {
            int i = p * 256 + tid;
            int r = i >> 8, f = i & 255;
            ws[r * 257 + f] = w[(size_t)(ch * 64 + r) * Fv + f];
        }
        __syncthreads();

        const float* w0 = ws + cl * 257;
        const float* w1 = ws + (cl + 32) * 257;
        const float* xb = xs + tg * 4 * 256;
        float a0[4] = {0.f, 0.f, 0.f, 0.f}, a1[4] = {0.f, 0.f, 0.f, 0.f};
        #pragma unroll 4
        for (int f = 0; f < 256; f++) {
            float wv0 = w0[f], wv1 = w1[f];
            #pragma unroll
            for (int j = 0; j < 4; j++) {
                float xv = xb[j * 256 + f];
                a0[j] = fmaf(wv0, xv, a0[j]);
                a1[j] = fmaf(wv1, xv, a1[j]);
            }
        }
        int k0 = ch * 64 + cl, k1 = k0 + 32;
        float w20 = __ldg(&g_w2[k0]), w21 = __ldg(&g_w2[k1]);
        #pragma unroll
        for (int j = 0; j < 4; j++) {
            float s0 = fmaf(-2.f, a0[j], w20);
            float s1 = fmaf(-2.f, a1[j], w21);
            float bs = s0; int bi = k0;
            if (s1 < s0) { bs = s1; bi = k1; }
            #pragma unroll
            for (int o = 16; o > 0; o >>= 1) {
                float os = __shfl_down_sync(0xffffffffu, bs, o);
                int   oi = __shfl_down_sync(0xffffffffu, bi, o);
                if (os < bs || (os == bs && oi < bi)) { bs = os; bi = oi; }
            }
            if (cl == 0) {
                g_fs[grp][ch][tg * 4 + j] = bs;
                g_fi[grp][ch][tg * 4 + j] = bi;
            }
        }
    }
}

__global__ void __launch_bounds__(256) vq_fixmerge() {
    const int n1 = g_n1;
    for (int p = blockIdx.x * 256 + threadIdx.x; p < n1; p += gridDim.x * 256) {
        int grp = p >> 5, slot = p & 31;
        float bs = g_fs[grp][0][slot]; int bi = g_fi[grp][0][slot];
        #pragma unroll
        for (int ch = 1; ch < 16; ch++) {
            float s = g_fs[grp][ch][slot]; int ii = g_fi[grp][ch][slot];
            if (s < bs || (s == bs && ii < bi)) { bs = s; bi = ii; }
        }
        int tok = g_list[p];
        g_idx[tok]  = bi;
        g_mind[tok] = (g_x2[tok] + bs) * (1.0f / (float)Fv);
    }
}

// ---------------- gather: out[b][f][t] = w[idx][f] ----------------
__global__ void __launch_bounds__(256) vq_gather(const float* __restrict__ w,
                                                 float* __restrict__ out) {
    int m0 = blockIdx.x * 128;
    int tok = threadIdx.x & 127, fg = threadIdx.x >> 7;
    int k = g_idx[m0 + tok];
    int bb = m0 >> 11, t = (m0 & 2047) + tok;
    const float* wr = w + (size_t)k * Fv + fg * 128;
    float* og = out + (size_t)bb * Fv * Tv + (size_t)(fg * 128) * Tv + t;
    #pragma unroll 4
    for (int i = 0; i < 128; i++) og[(size_t)i * Tv] = __ldg(wr + i);
}

// ---------------- loss: two-stage deterministic reduction ----------------
__global__ void __launch_bounds__(256) vq_loss1() {
    __shared__ float sh[256];
    int base = blockIdx.x * 1024;
    float s = 0.f;
    #pragma unroll
    for (int p = 0; p < 4; p++) s += g_mind[base + p * 256 + threadIdx.x];
    sh[threadIdx.x] = s;
    __syncthreads();
    #pragma unroll
    for (int o = 128; o > 0; o >>= 1) {
        if (threadIdx.x < o) sh[threadIdx.x] += sh[threadIdx.x + o];
        __syncthreads();
    }
    if (threadIdx.x == 0) g_lpart[blockIdx.x] = sh[0];
}
__global__ void vq_loss2(float* __restrict__ out, int out_size) {
    if (threadIdx.x == 0) {
        float s = 0.f;
        #pragma unroll
        for (int i = 0; i < 64; i++) s += g_lpart[i];
        float mean = s / (float)MTOT;
        const long long N = (long long)Bv * Fv * Tv;
        if (out_size > N)     out[N]     = mean;
        if (out_size > N + 1) out[N + 1] = mean;
    }
}

// ---------------------------------------------------------------------------
extern "C" void kernel_launch(void* const* d_in, const int* in_sizes, int n_in,
                              void* d_out, int out_size) {
    const float* x = (const float*)d_in[0];
    const float* w = (const float*)d_in[1];
    float* out = (float*)d_out;

    cudaFuncSetAttribute(x_prep, cudaFuncAttributeMaxDynamicSharedMemorySize, 256 * 65 * 4);
    cudaFuncSetAttribute(vq_hmma, cudaFuncAttributeMaxDynamicSharedMemorySize, SA_TOTAL);

    zero_init<<<1, 1>>>();
    w_prep<<<Kv, 256>>>(w);
    x_prep<<<MTOT / 64, 256, 256 * 65 * 4>>>(x);
    vq_hmma<<<MTOT / 128, 512, SA_TOTAL>>>();
    vq_fix2<<<dim3(16, 128), 256>>>(w);
    vq_fixmerge<<<64, 256>>>();
    vq_gather<<<MTOT / 128, 256>>>(w, out);
    vq_loss1<<<64, 256>>>();
    vq_loss2<<<1, 32>>>(out, out_size);
}